// round 1
// baseline (speedup 1.0000x reference)
#include <cuda_runtime.h>
#include <math.h>
#include <math_constants.h>

#define T_TOK 2048
#define H_DIM 1024
#define F_DIM 4096
#define E_NUM 8
#define MAXPAIRS (2 * T_TOK)

// ---------------- scratch (__device__ globals; no runtime alloc) ----------------
__device__ float g_logits[T_TOK * E_NUM];
__device__ int   g_ea[T_TOK];
__device__ int   g_eb[T_TOK];
__device__ float g_ca[T_TOK];
__device__ float g_cb[T_TOK];
__device__ int   g_cnt[E_NUM];
__device__ int   g_off[E_NUM];
__device__ int   g_cur[E_NUM];
__device__ int   g_tok[MAXPAIRS];
__device__ float g_coef[MAXPAIRS];
__device__ float g_h[(size_t)MAXPAIRS * F_DIM];   // 64 MB intermediate silu(x@w1)*(x@w3)

// ---------------- K0: zero output + counters ----------------
__global__ void zero_kernel(float* __restrict__ out) {
    int n = T_TOK * H_DIM;
    for (int i = blockIdx.x * blockDim.x + threadIdx.x; i < n;
         i += gridDim.x * blockDim.x)
        out[i] = 0.0f;
    if (blockIdx.x == 0 && threadIdx.x < E_NUM) g_cnt[threadIdx.x] = 0;
}

// ---------------- K1: router logits = x @ gate_w ----------------
__global__ __launch_bounds__(256) void router_kernel(
    const float* __restrict__ x, const float* __restrict__ gw,
    float* __restrict__ out_logits) {
    // gate_w transposed into smem: sgw[e][h]
    __shared__ float sgw[E_NUM * H_DIM];   // 32 KB
    for (int i = threadIdx.x; i < H_DIM * E_NUM; i += 256) {
        int h = i >> 3, e = i & 7;
        sgw[e * H_DIM + h] = gw[i];
    }
    __syncthreads();

    int warp = threadIdx.x >> 5, lane = threadIdx.x & 31;
    int t = blockIdx.x * 8 + warp;
    if (t >= T_TOK) return;
    const float* xr = x + (size_t)t * H_DIM;

    float acc[E_NUM];
#pragma unroll
    for (int e = 0; e < E_NUM; e++) acc[e] = 0.0f;

    for (int h = lane; h < H_DIM; h += 32) {
        float xv = xr[h];
#pragma unroll
        for (int e = 0; e < E_NUM; e++) acc[e] += xv * sgw[e * H_DIM + h];
    }
#pragma unroll
    for (int e = 0; e < E_NUM; e++) {
#pragma unroll
        for (int o = 16; o > 0; o >>= 1)
            acc[e] += __shfl_down_sync(0xffffffffu, acc[e], o);
    }
    if (lane == 0) {
#pragma unroll
        for (int e = 0; e < E_NUM; e++) {
            g_logits[t * E_NUM + e] = acc[e];
            out_logits[t * E_NUM + e] = acc[e];
        }
    }
}

// ---------------- K2: sparsemixer routing + bug-faithful combine coefs ----------------
__global__ void route_kernel() {
    int t = blockIdx.x * blockDim.x + threadIdx.x;
    if (t >= T_TOK) return;
    float s[E_NUM];
#pragma unroll
    for (int e = 0; e < E_NUM; e++) s[e] = g_logits[t * E_NUM + e];

    // first argmax (first occurrence)
    float mx = s[0];
    int i0 = 0;
#pragma unroll
    for (int e = 1; e < E_NUM; e++)
        if (s[e] > mx) { mx = s[e]; i0 = e; }

    // softmax over entries passing threshold mask
    float denom = 0.0f;
#pragma unroll
    for (int e = 0; e < E_NUM; e++) {
        float f = fmaxf(fabsf(s[e]), mx);
        if (!((mx - s[e]) / f > 0.02f)) denom += expf(s[e] - mx);
    }
    float w0 = 1.0f / denom;   // exp(s[i0]-mx)=1

    // second argmax over masked scores (i0 removed)
    float mx2 = -CUDART_INF_F;
    int i1 = 0;
#pragma unroll
    for (int e = 0; e < E_NUM; e++)
        if (e != i0 && s[e] > mx2) { mx2 = s[e]; i1 = e; }

    float denom2 = 0.0f;
#pragma unroll
    for (int e = 0; e < E_NUM; e++) {
        if (e == i0) continue;   // masked_scores[i0] = -inf -> contributes 0
        float f = fmaxf(fabsf(s[e]), mx2);
        if (!((mx2 - s[e]) / f > 0.02f)) denom2 += expf(s[e] - mx2);
    }
    float w1v = 1.0f / denom2;

    // dense-table quirk: final = dense[t,0]*out[i0] + dense[t,1]*out[i1]
    float c0 = (i0 == 0) ? w0 : ((i1 == 0) ? w1v : 0.0f);
    float c1 = (i0 == 1) ? w0 : ((i1 == 1) ? w1v : 0.0f);

    g_ea[t] = i0; g_ca[t] = c0;
    g_eb[t] = i1; g_cb[t] = c1;
    if (c0 != 0.0f) atomicAdd(&g_cnt[i0], 1);
    if (c1 != 0.0f) atomicAdd(&g_cnt[i1], 1);
}

// ---------------- K3: prefix sum (tiny) ----------------
__global__ void prefix_kernel() {
    int acc = 0;
    for (int e = 0; e < E_NUM; e++) {
        g_off[e] = acc;
        g_cur[e] = acc;
        acc += g_cnt[e];
    }
}

// ---------------- K4: compact (token, coef) per expert ----------------
__global__ void scatter_kernel() {
    int t = blockIdx.x * blockDim.x + threadIdx.x;
    if (t >= T_TOK) return;
    float c0 = g_ca[t];
    if (c0 != 0.0f) {
        int slot = atomicAdd(&g_cur[g_ea[t]], 1);
        g_tok[slot] = t; g_coef[slot] = c0;
    }
    float c1 = g_cb[t];
    if (c1 != 0.0f) {
        int slot = atomicAdd(&g_cur[g_eb[t]], 1);
        g_tok[slot] = t; g_coef[slot] = c1;
    }
}

// ---------------- K5: h = silu(Xe @ W1[e]) * (Xe @ W3[e]) ----------------
// tile: M=128, N=64, K=16; 256 threads; micro 8x4, two output matrices
__global__ __launch_bounds__(256) void gemm1_kernel(
    const float* __restrict__ x, const float* __restrict__ w1,
    const float* __restrict__ w3) {
    const int e = blockIdx.z;
    const int cnt = g_cnt[e];
    const int m0 = blockIdx.y * 128;
    if (m0 >= cnt) return;
    const int off = g_off[e];
    const int n0 = blockIdx.x * 64;
    const float* __restrict__ W1 = w1 + (size_t)e * H_DIM * F_DIM;
    const float* __restrict__ W3 = w3 + (size_t)e * H_DIM * F_DIM;

    __shared__ float As[128][17];
    __shared__ __align__(16) float B1s[16][64];
    __shared__ __align__(16) float B3s[16][64];
    __shared__ int stok[128];

    const int tid = threadIdx.x;
    if (tid < 128) {
        int r = m0 + tid;
        stok[tid] = g_tok[off + (r < cnt ? r : cnt - 1)];
    }
    __syncthreads();

    float acc1[8][4] = {};
    float acc3[8][4] = {};
    const int ty = tid >> 4;   // 0..15, 8 rows each
    const int tx = tid & 15;   // 0..15, 4 cols each

    for (int k0 = 0; k0 < H_DIM; k0 += 16) {
#pragma unroll
        for (int i = 0; i < 8; i++) {
            int idx = tid + i * 256;
            int row = idx >> 4;
            int kk = idx & 15;
            As[row][kk] = x[(size_t)stok[row] * H_DIM + k0 + kk];
        }
#pragma unroll
        for (int i = 0; i < 4; i++) {
            int idx = tid + i * 256;
            int kk = idx >> 6;
            int nn = idx & 63;
            size_t g = (size_t)(k0 + kk) * F_DIM + n0 + nn;
            B1s[kk][nn] = W1[g];
            B3s[kk][nn] = W3[g];
        }
        __syncthreads();
#pragma unroll
        for (int kk = 0; kk < 16; kk++) {
            float a[8];
#pragma unroll
            for (int i = 0; i < 8; i++) a[i] = As[ty * 8 + i][kk];
            float4 b1 = *(const float4*)&B1s[kk][tx * 4];
            float4 b3 = *(const float4*)&B3s[kk][tx * 4];
#pragma unroll
            for (int i = 0; i < 8; i++) {
                acc1[i][0] += a[i] * b1.x; acc1[i][1] += a[i] * b1.y;
                acc1[i][2] += a[i] * b1.z; acc1[i][3] += a[i] * b1.w;
                acc3[i][0] += a[i] * b3.x; acc3[i][1] += a[i] * b3.y;
                acc3[i][2] += a[i] * b3.z; acc3[i][3] += a[i] * b3.w;
            }
        }
        __syncthreads();
    }
#pragma unroll
    for (int i = 0; i < 8; i++) {
        int row = m0 + ty * 8 + i;
        if (row < cnt) {
            size_t hb = (size_t)(off + row) * F_DIM + n0 + tx * 4;
#pragma unroll
            for (int j = 0; j < 4; j++) {
                float g = acc1[i][j];
                float u = acc3[i][j];
                float sg = g / (1.0f + expf(-g));   // silu
                g_h[hb + j] = sg * u;
            }
        }
    }
}

// ---------------- K6: out += coef * (h @ W2[e]) ----------------
// tile: M=64, N=64, K=16; 256 threads; micro 4x4
__global__ __launch_bounds__(256) void gemm2_kernel(
    const float* __restrict__ w2, float* __restrict__ out) {
    const int e = blockIdx.z;
    const int cnt = g_cnt[e];
    const int m0 = blockIdx.y * 64;
    if (m0 >= cnt) return;
    const int off = g_off[e];
    const int n0 = blockIdx.x * 64;
    const float* __restrict__ W2 = w2 + (size_t)e * F_DIM * H_DIM;

    __shared__ float As[64][17];
    __shared__ __align__(16) float Bs[16][64];

    const int tid = threadIdx.x;
    const int ty = tid >> 4, tx = tid & 15;
    float acc[4][4] = {};

    for (int k0 = 0; k0 < F_DIM; k0 += 16) {
#pragma unroll
        for (int i = 0; i < 4; i++) {
            int idx = tid + i * 256;
            int row = idx >> 4;
            int kk = idx & 15;
            int r = m0 + row;
            if (r >= cnt) r = cnt - 1;
            As[row][kk] = g_h[(size_t)(off + r) * F_DIM + k0 + kk];
        }
#pragma unroll
        for (int i = 0; i < 4; i++) {
            int idx = tid + i * 256;
            int kk = idx >> 6;
            int nn = idx & 63;
            Bs[kk][nn] = W2[(size_t)(k0 + kk) * H_DIM + n0 + nn];
        }
        __syncthreads();
#pragma unroll
        for (int kk = 0; kk < 16; kk++) {
            float a[4];
#pragma unroll
            for (int i = 0; i < 4; i++) a[i] = As[ty * 4 + i][kk];
            float4 b = *(const float4*)&Bs[kk][tx * 4];
#pragma unroll
            for (int i = 0; i < 4; i++) {
                acc[i][0] += a[i] * b.x; acc[i][1] += a[i] * b.y;
                acc[i][2] += a[i] * b.z; acc[i][3] += a[i] * b.w;
            }
        }
        __syncthreads();
    }
#pragma unroll
    for (int i = 0; i < 4; i++) {
        int row = m0 + ty * 4 + i;
        if (row < cnt) {
            int t = g_tok[off + row];
            float c = g_coef[off + row];
            float* dst = out + (size_t)t * H_DIM + n0 + tx * 4;
#pragma unroll
            for (int j = 0; j < 4; j++) atomicAdd(&dst[j], acc[i][j] * c);
        }
    }
}

// ---------------- launch ----------------
extern "C" void kernel_launch(void* const* d_in, const int* in_sizes, int n_in,
                              void* d_out, int out_size) {
    const float* x  = (const float*)d_in[0];   // hidden_states [2,1024,1024]
    const float* gw = (const float*)d_in[1];   // gate_w [1024,8]
    const float* w1 = (const float*)d_in[2];   // [8,1024,4096]
    const float* w3 = (const float*)d_in[3];   // [8,1024,4096]
    const float* w2 = (const float*)d_in[4];   // [8,4096,1024]
    float* out = (float*)d_out;
    float* out_logits = out + (size_t)T_TOK * H_DIM;   // router_logits after final

    zero_kernel<<<2048, 256>>>(out);
    router_kernel<<<T_TOK / 8, 256>>>(x, gw, out_logits);
    route_kernel<<<T_TOK / 256, 256>>>();
    prefix_kernel<<<1, 1>>>();
    scatter_kernel<<<T_TOK / 256, 256>>>();
    gemm1_kernel<<<dim3(F_DIM / 64, T_TOK / 128, E_NUM), 256>>>(x, w1, w3);
    gemm2_kernel<<<dim3(H_DIM / 64, T_TOK / 64, E_NUM), 256>>>(w2, out);
}

// round 3
// speedup vs baseline: 2.6167x; 2.6167x over previous
#include <cuda_runtime.h>
#include <math.h>
#include <math_constants.h>
#include <cstdint>

#define T_TOK 2048
#define H_DIM 1024
#define F_DIM 4096
#define E_NUM 8
#define MAXPAIRS (2 * T_TOK)

// ================= scratch (__device__ globals; no runtime alloc) =================
__device__ float g_logits[T_TOK * E_NUM];
__device__ int   g_ea[T_TOK];
__device__ int   g_eb[T_TOK];
__device__ float g_ca[T_TOK];
__device__ float g_cb[T_TOK];
__device__ int   g_cnt[E_NUM];
__device__ int   g_off[E_NUM];
__device__ int   g_cur[E_NUM];
__device__ int   g_tok[MAXPAIRS];
__device__ float g_coef[MAXPAIRS];
__device__ float g_h[(size_t)MAXPAIRS * F_DIM];   // 64 MB intermediate silu(x@w1)*(x@w3)

// ================= helpers =================
__device__ __forceinline__ uint32_t f2tf(float f) {
    uint32_t u;
    asm("cvt.rna.tf32.f32 %0, %1;" : "=r"(u) : "f"(f));
    return u;
}
__device__ __forceinline__ uint4 f2tf4(float4 v) {
    uint4 u;
    u.x = f2tf(v.x); u.y = f2tf(v.y); u.z = f2tf(v.z); u.w = f2tf(v.w);
    return u;
}
#define MMA_TF32(d, a, b0, b1)                                                           \
    asm volatile(                                                                        \
        "mma.sync.aligned.m16n8k8.row.col.f32.tf32.tf32.f32 "                            \
        "{%0,%1,%2,%3},{%4,%5,%6,%7},{%8,%9},{%0,%1,%2,%3};"                             \
        : "+f"((d)[0]), "+f"((d)[1]), "+f"((d)[2]), "+f"((d)[3])                         \
        : "r"((a)[0]), "r"((a)[1]), "r"((a)[2]), "r"((a)[3]), "r"(b0), "r"(b1))

// ================= K0: zero output + counters =================
__global__ void zero_kernel(float* __restrict__ out) {
    int n = T_TOK * H_DIM;
    for (int i = blockIdx.x * blockDim.x + threadIdx.x; i < n; i += gridDim.x * blockDim.x)
        out[i] = 0.0f;
    if (blockIdx.x == 0 && threadIdx.x < E_NUM) g_cnt[threadIdx.x] = 0;
}

// ================= K1: router logits = x @ gate_w =================
__global__ __launch_bounds__(256) void router_kernel(
    const float* __restrict__ x, const float* __restrict__ gw, float* __restrict__ out_logits) {
    __shared__ float sgw[E_NUM * H_DIM];
    for (int i = threadIdx.x; i < H_DIM * E_NUM; i += 256) {
        int h = i >> 3, e = i & 7;
        sgw[e * H_DIM + h] = gw[i];
    }
    __syncthreads();
    int warp = threadIdx.x >> 5, lane = threadIdx.x & 31;
    int t = blockIdx.x * 8 + warp;
    if (t >= T_TOK) return;
    const float* xr = x + (size_t)t * H_DIM;
    float acc[E_NUM];
#pragma unroll
    for (int e = 0; e < E_NUM; e++) acc[e] = 0.0f;
    for (int h = lane; h < H_DIM; h += 32) {
        float xv = xr[h];
#pragma unroll
        for (int e = 0; e < E_NUM; e++) acc[e] += xv * sgw[e * H_DIM + h];
    }
#pragma unroll
    for (int e = 0; e < E_NUM; e++) {
#pragma unroll
        for (int o = 16; o > 0; o >>= 1) acc[e] += __shfl_down_sync(0xffffffffu, acc[e], o);
    }
    if (lane == 0) {
#pragma unroll
        for (int e = 0; e < E_NUM; e++) {
            g_logits[t * E_NUM + e] = acc[e];
            out_logits[t * E_NUM + e] = acc[e];
        }
    }
}

// ================= K2: sparsemixer routing (bug-faithful combine) =================
__global__ void route_kernel() {
    int t = blockIdx.x * blockDim.x + threadIdx.x;
    if (t >= T_TOK) return;
    float s[E_NUM];
#pragma unroll
    for (int e = 0; e < E_NUM; e++) s[e] = g_logits[t * E_NUM + e];
    float mx = s[0];
    int i0 = 0;
#pragma unroll
    for (int e = 1; e < E_NUM; e++)
        if (s[e] > mx) { mx = s[e]; i0 = e; }
    float denom = 0.0f;
#pragma unroll
    for (int e = 0; e < E_NUM; e++) {
        float f = fmaxf(fabsf(s[e]), mx);
        if (!((mx - s[e]) / f > 0.02f)) denom += expf(s[e] - mx);
    }
    float w0 = 1.0f / denom;
    float mx2 = -CUDART_INF_F;
    int i1 = 0;
#pragma unroll
    for (int e = 0; e < E_NUM; e++)
        if (e != i0 && s[e] > mx2) { mx2 = s[e]; i1 = e; }
    float denom2 = 0.0f;
#pragma unroll
    for (int e = 0; e < E_NUM; e++) {
        if (e == i0) continue;
        float f = fmaxf(fabsf(s[e]), mx2);
        if (!((mx2 - s[e]) / f > 0.02f)) denom2 += expf(s[e] - mx2);
    }
    float w1v = 1.0f / denom2;
    float c0 = (i0 == 0) ? w0 : ((i1 == 0) ? w1v : 0.0f);
    float c1 = (i0 == 1) ? w0 : ((i1 == 1) ? w1v : 0.0f);
    g_ea[t] = i0; g_ca[t] = c0;
    g_eb[t] = i1; g_cb[t] = c1;
    if (c0 != 0.0f) atomicAdd(&g_cnt[i0], 1);
    if (c1 != 0.0f) atomicAdd(&g_cnt[i1], 1);
}

// ================= K3/K4: prefix + compaction =================
__global__ void prefix_kernel() {
    int acc = 0;
    for (int e = 0; e < E_NUM; e++) {
        g_off[e] = acc;
        g_cur[e] = acc;
        acc += g_cnt[e];
    }
}
__global__ void scatter_kernel() {
    int t = blockIdx.x * blockDim.x + threadIdx.x;
    if (t >= T_TOK) return;
    float c0 = g_ca[t];
    if (c0 != 0.0f) {
        int slot = atomicAdd(&g_cur[g_ea[t]], 1);
        g_tok[slot] = t; g_coef[slot] = c0;
    }
    float c1 = g_cb[t];
    if (c1 != 0.0f) {
        int slot = atomicAdd(&g_cur[g_eb[t]], 1);
        g_tok[slot] = t; g_coef[slot] = c1;
    }
}

// ================= GEMM smem layouts =================
// A tile (64 rows x 32 k) tf32, row stride 36 (bank-free frag loads: 4*gid+tg)
// B tile (32 k x 128 n) tf32, row stride 136 (bank-free frag loads: 8*tg+gid)
#define A_STRIDE 36
#define B_STRIDE 136
#define A_BUF_U32 (64 * A_STRIDE)         // 2304
#define B_BUF_U32 (32 * B_STRIDE)         // 4352
#define G1_AS_OFF 256
#define G1_B1_OFF (G1_AS_OFF + 2 * A_BUF_U32 * 4)            // 18688
#define G1_B3_OFF (G1_B1_OFF + 2 * B_BUF_U32 * 4)            // 53504
#define G1_SMEM   (G1_B3_OFF + 2 * B_BUF_U32 * 4)            // 88320
#define G2_AS_OFF 256
#define G2_B_OFF  (G2_AS_OFF + 2 * A_BUF_U32 * 4)            // 18688
#define G2_SMEM   (G2_B_OFF + 2 * B_BUF_U32 * 4)             // 53504

// ================= GEMM1: h = silu(Xe@W1) * (Xe@W3) =================
// block tile M=64, N=128, Kc=32; 8 warps (2x4), warp tile 32x32 per matrix
__global__ __launch_bounds__(256) void gemm1_kernel(
    const float* __restrict__ x, const float* __restrict__ w1, const float* __restrict__ w3) {
    const int e = blockIdx.z;
    const int cnt = g_cnt[e];
    const int m0 = blockIdx.y * 64;
    if (m0 >= cnt) return;
    const int off = g_off[e];
    const int n0 = blockIdx.x * 128;
    const float* __restrict__ W1 = w1 + (size_t)e * H_DIM * F_DIM;
    const float* __restrict__ W3 = w3 + (size_t)e * H_DIM * F_DIM;

    extern __shared__ char sm[];
    int* stok = (int*)sm;
    uint32_t* AsB = (uint32_t*)(sm + G1_AS_OFF);
    uint32_t* B1B = (uint32_t*)(sm + G1_B1_OFF);
    uint32_t* B3B = (uint32_t*)(sm + G1_B3_OFF);

    const int tid = threadIdx.x, wid = tid >> 5, lane = tid & 31;
    const int gid = lane >> 2, tg = lane & 3;
    const int wm = wid >> 2, wn = wid & 3;

    if (tid < 64) {
        int r = m0 + tid;
        stok[tid] = g_tok[off + (r < cnt ? r : cnt - 1)];
    }
    __syncthreads();

    float acc1[2][4][4] = {};
    float acc3[2][4][4] = {};

#define G1_LOAD(c)                                                                            \
    do {                                                                                      \
        int _b = (c) & 1;                                                                     \
        int _k0 = (c) * 32;                                                                   \
        uint32_t* _A = AsB + _b * A_BUF_U32;                                                  \
        uint32_t* _B1 = B1B + _b * B_BUF_U32;                                                 \
        uint32_t* _B3 = B3B + _b * B_BUF_U32;                                                 \
        _Pragma("unroll") for (int _i = 0; _i < 2; _i++) {                                    \
            int _idx = tid + _i * 256;                                                        \
            int _row = _idx >> 3, _c4 = _idx & 7;                                             \
            float4 _v = *(const float4*)(x + (size_t)stok[_row] * H_DIM + _k0 + _c4 * 4);     \
            *(uint4*)(_A + _row * A_STRIDE + _c4 * 4) = f2tf4(_v);                            \
        }                                                                                     \
        _Pragma("unroll") for (int _i = 0; _i < 4; _i++) {                                    \
            int _idx = tid + _i * 256;                                                        \
            int _kk = _idx >> 5, _f4 = _idx & 31;                                             \
            size_t _g = (size_t)(_k0 + _kk) * F_DIM + n0 + _f4 * 4;                           \
            *(uint4*)(_B1 + _kk * B_STRIDE + _f4 * 4) = f2tf4(*(const float4*)(W1 + _g));     \
            *(uint4*)(_B3 + _kk * B_STRIDE + _f4 * 4) = f2tf4(*(const float4*)(W3 + _g));     \
        }                                                                                     \
    } while (0)

    G1_LOAD(0);
    __syncthreads();
    for (int c = 0; c < 32; c++) {
        if (c + 1 < 32) G1_LOAD(c + 1);
        const int b = c & 1;
        const uint32_t* A = AsB + b * A_BUF_U32;
        const uint32_t* B1 = B1B + b * B_BUF_U32;
        const uint32_t* B3 = B3B + b * B_BUF_U32;
#pragma unroll
        for (int ks = 0; ks < 4; ks++) {
            uint32_t a[2][4];
#pragma unroll
            for (int mt = 0; mt < 2; mt++) {
                int rb = (wm * 32 + mt * 16 + gid) * A_STRIDE + ks * 8 + tg;
                a[mt][0] = A[rb];
                a[mt][1] = A[rb + 8 * A_STRIDE];
                a[mt][2] = A[rb + 4];
                a[mt][3] = A[rb + 8 * A_STRIDE + 4];
            }
#pragma unroll
            for (int nt = 0; nt < 4; nt++) {
                int bb = (ks * 8 + tg) * B_STRIDE + wn * 32 + nt * 8 + gid;
                uint32_t b10 = B1[bb], b11 = B1[bb + 4 * B_STRIDE];
                uint32_t b30 = B3[bb], b31 = B3[bb + 4 * B_STRIDE];
#pragma unroll
                for (int mt = 0; mt < 2; mt++) {
                    MMA_TF32(acc1[mt][nt], a[mt], b10, b11);
                    MMA_TF32(acc3[mt][nt], a[mt], b30, b31);
                }
            }
        }
        __syncthreads();
    }

    // epilogue: silu(acc1)*acc3 -> g_h
#pragma unroll
    for (int mt = 0; mt < 2; mt++) {
#pragma unroll
        for (int half = 0; half < 2; half++) {
            int row = m0 + wm * 32 + mt * 16 + half * 8 + gid;
            if (row < cnt) {
                float* hp = g_h + (size_t)(off + row) * F_DIM + n0 + wn * 32 + tg * 2;
#pragma unroll
                for (int nt = 0; nt < 4; nt++) {
                    float g0 = acc1[mt][nt][half * 2 + 0];
                    float g1 = acc1[mt][nt][half * 2 + 1];
                    float u0 = acc3[mt][nt][half * 2 + 0];
                    float u1 = acc3[mt][nt][half * 2 + 1];
                    float o0 = u0 * (g0 / (1.0f + expf(-g0)));
                    float o1 = u1 * (g1 / (1.0f + expf(-g1)));
                    *(float2*)(hp + nt * 8) = make_float2(o0, o1);
                }
            }
        }
    }
}

// ================= GEMM2: out += coef * (h @ W2) =================
// block tile M=64, N=128, Kc=32, K=4096 (128 chunks)
__global__ __launch_bounds__(256) void gemm2_kernel(
    const float* __restrict__ w2, float* __restrict__ out) {
    const int e = blockIdx.z;
    const int cnt = g_cnt[e];
    const int m0 = blockIdx.y * 64;
    if (m0 >= cnt) return;
    const int off = g_off[e];
    const int n0 = blockIdx.x * 128;
    const float* __restrict__ W2 = w2 + (size_t)e * F_DIM * H_DIM;

    extern __shared__ char sm[];
    int* srow = (int*)sm;   // clamped absolute slot
    uint32_t* AsB = (uint32_t*)(sm + G2_AS_OFF);
    uint32_t* BB  = (uint32_t*)(sm + G2_B_OFF);

    const int tid = threadIdx.x, wid = tid >> 5, lane = tid & 31;
    const int gid = lane >> 2, tg = lane & 3;
    const int wm = wid >> 2, wn = wid & 3;

    if (tid < 64) {
        int r = m0 + tid;
        srow[tid] = off + (r < cnt ? r : cnt - 1);
    }
    __syncthreads();

    float acc[2][4][4] = {};

#define G2_LOAD(c)                                                                            \
    do {                                                                                      \
        int _b = (c) & 1;                                                                     \
        int _k0 = (c) * 32;                                                                   \
        uint32_t* _A = AsB + _b * A_BUF_U32;                                                  \
        uint32_t* _B = BB + _b * B_BUF_U32;                                                   \
        _Pragma("unroll") for (int _i = 0; _i < 2; _i++) {                                    \
            int _idx = tid + _i * 256;                                                        \
            int _row = _idx >> 3, _c4 = _idx & 7;                                             \
            float4 _v = *(const float4*)(g_h + (size_t)srow[_row] * F_DIM + _k0 + _c4 * 4);   \
            *(uint4*)(_A + _row * A_STRIDE + _c4 * 4) = f2tf4(_v);                            \
        }                                                                                     \
        _Pragma("unroll") for (int _i = 0; _i < 4; _i++) {                                    \
            int _idx = tid + _i * 256;                                                        \
            int _kk = _idx >> 5, _f4 = _idx & 31;                                             \
            size_t _g = (size_t)(_k0 + _kk) * H_DIM + n0 + _f4 * 4;                           \
            *(uint4*)(_B + _kk * B_STRIDE + _f4 * 4) = f2tf4(*(const float4*)(W2 + _g));      \
        }                                                                                     \
    } while (0)

    G2_LOAD(0);
    __syncthreads();
    for (int c = 0; c < 128; c++) {
        if (c + 1 < 128) G2_LOAD(c + 1);
        const int b = c & 1;
        const uint32_t* A = AsB + b * A_BUF_U32;
        const uint32_t* B = BB + b * B_BUF_U32;
#pragma unroll
        for (int ks = 0; ks < 4; ks++) {
            uint32_t a[2][4];
#pragma unroll
            for (int mt = 0; mt < 2; mt++) {
                int rb = (wm * 32 + mt * 16 + gid) * A_STRIDE + ks * 8 + tg;
                a[mt][0] = A[rb];
                a[mt][1] = A[rb + 8 * A_STRIDE];
                a[mt][2] = A[rb + 4];
                a[mt][3] = A[rb + 8 * A_STRIDE + 4];
            }
#pragma unroll
            for (int nt = 0; nt < 4; nt++) {
                int bb = (ks * 8 + tg) * B_STRIDE + wn * 32 + nt * 8 + gid;
                uint32_t b0 = B[bb], b1 = B[bb + 4 * B_STRIDE];
#pragma unroll
                for (int mt = 0; mt < 2; mt++) MMA_TF32(acc[mt][nt], a[mt], b0, b1);
            }
        }
        __syncthreads();
    }

    // epilogue: atomic scaled scatter
#pragma unroll
    for (int mt = 0; mt < 2; mt++) {
#pragma unroll
        for (int half = 0; half < 2; half++) {
            int row = m0 + wm * 32 + mt * 16 + half * 8 + gid;
            if (row < cnt) {
                int slot = off + row;
                int tok = g_tok[slot];
                float coef = g_coef[slot];
                float* dst = out + (size_t)tok * H_DIM + n0 + wn * 32 + tg * 2;
#pragma unroll
                for (int nt = 0; nt < 4; nt++) {
                    atomicAdd(dst + nt * 8 + 0, acc[mt][nt][half * 2 + 0] * coef);
                    atomicAdd(dst + nt * 8 + 1, acc[mt][nt][half * 2 + 1] * coef);
                }
            }
        }
    }
}

// ================= launch =================
extern "C" void kernel_launch(void* const* d_in, const int* in_sizes, int n_in,
                              void* d_out, int out_size) {
    const float* x  = (const float*)d_in[0];
    const float* gw = (const float*)d_in[1];
    const float* w1 = (const float*)d_in[2];
    const float* w3 = (const float*)d_in[3];
    const float* w2 = (const float*)d_in[4];
    float* out = (float*)d_out;
    float* out_logits = out + (size_t)T_TOK * H_DIM;

    cudaFuncSetAttribute(gemm1_kernel, cudaFuncAttributeMaxDynamicSharedMemorySize, G1_SMEM);
    cudaFuncSetAttribute(gemm2_kernel, cudaFuncAttributeMaxDynamicSharedMemorySize, G2_SMEM);

    zero_kernel<<<2048, 256>>>(out);
    router_kernel<<<T_TOK / 8, 256>>>(x, gw, out_logits);
    route_kernel<<<T_TOK / 256, 256>>>();
    prefix_kernel<<<1, 1>>>();
    scatter_kernel<<<T_TOK / 256, 256>>>();
    gemm1_kernel<<<dim3(F_DIM / 128, T_TOK / 64, E_NUM), 256, G1_SMEM>>>(x, w1, w3);
    gemm2_kernel<<<dim3(H_DIM / 128, T_TOK / 64, E_NUM), 256, G2_SMEM>>>(w2, out);
}

// round 4
// speedup vs baseline: 4.0177x; 1.5354x over previous
#include <cuda_runtime.h>
#include <math.h>
#include <math_constants.h>
#include <cstdint>

#define T_TOK 2048
#define H_DIM 1024
#define F_DIM 4096
#define E_NUM 8
#define MAXPAIRS (2 * T_TOK)

// ================= scratch (__device__ globals; no runtime alloc) =================
__device__ float g_logits[T_TOK * E_NUM];
__device__ int   g_cnt[E_NUM];
__device__ int   g_off[E_NUM];
__device__ int   g_tok[MAXPAIRS];
__device__ float g_coef[MAXPAIRS];
__device__ float g_h[(size_t)MAXPAIRS * F_DIM];   // intermediate silu(x@w1)*(x@w3)

// ================= helpers =================
__device__ __forceinline__ uint32_t smem_u32(const void* p) {
    uint32_t a;
    asm("{ .reg .u64 t; cvta.to.shared.u64 t, %1; cvt.u32.u64 %0, t; }" : "=r"(a) : "l"(p));
    return a;
}
__device__ __forceinline__ uint32_t f2tf(float f) {
    uint32_t u;
    asm("cvt.rna.tf32.f32 %0, %1;" : "=r"(u) : "f"(f));
    return u;
}
#define CPA(dst, src) \
    asm volatile("cp.async.cg.shared.global [%0], [%1], 16;" ::"r"(dst), "l"(src) : "memory")
#define CPA_COMMIT() asm volatile("cp.async.commit_group;" ::: "memory")
#define CPA_WAIT1()  asm volatile("cp.async.wait_group 1;" ::: "memory")
#define CPA_WAIT0()  asm volatile("cp.async.wait_group 0;" ::: "memory")
#define MMA_TF32(d, a, b0, b1)                                                           \
    asm volatile(                                                                        \
        "mma.sync.aligned.m16n8k8.row.col.f32.tf32.tf32.f32 "                            \
        "{%0,%1,%2,%3},{%4,%5,%6,%7},{%8,%9},{%0,%1,%2,%3};"                             \
        : "+f"((d)[0]), "+f"((d)[1]), "+f"((d)[2]), "+f"((d)[3])                         \
        : "r"((a)[0]), "r"((a)[1]), "r"((a)[2]), "r"((a)[3]), "r"(b0), "r"(b1))

// ================= K0: router logits + zero output rows =================
// CTA b: tokens b*8 .. b*8+7 ; zeroes their out rows, computes logits.
__global__ __launch_bounds__(256) void router_kernel(
    const float* __restrict__ x, const float* __restrict__ gw,
    float* __restrict__ out, float* __restrict__ out_logits) {
    __shared__ float sgw[E_NUM * H_DIM];
    for (int i = threadIdx.x; i < H_DIM * E_NUM; i += 256) {
        int h = i >> 3, e = i & 7;
        sgw[e * H_DIM + h] = gw[i];
    }
    // zero 8 output rows (8192 floats) for this CTA
    {
        float4 z = make_float4(0.f, 0.f, 0.f, 0.f);
        float4* dst = (float4*)(out + (size_t)blockIdx.x * 8 * H_DIM);
#pragma unroll
        for (int i = 0; i < 8; i++) dst[threadIdx.x + i * 256] = z;
    }
    __syncthreads();
    int warp = threadIdx.x >> 5, lane = threadIdx.x & 31;
    int t = blockIdx.x * 8 + warp;
    const float* xr = x + (size_t)t * H_DIM;
    float acc[E_NUM];
#pragma unroll
    for (int e = 0; e < E_NUM; e++) acc[e] = 0.0f;
    for (int h = lane; h < H_DIM; h += 32) {
        float xv = xr[h];
#pragma unroll
        for (int e = 0; e < E_NUM; e++) acc[e] += xv * sgw[e * H_DIM + h];
    }
#pragma unroll
    for (int e = 0; e < E_NUM; e++) {
#pragma unroll
        for (int o = 16; o > 0; o >>= 1) acc[e] += __shfl_down_sync(0xffffffffu, acc[e], o);
    }
    if (lane == 0) {
#pragma unroll
        for (int e = 0; e < E_NUM; e++) {
            g_logits[t * E_NUM + e] = acc[e];
            out_logits[t * E_NUM + e] = acc[e];
        }
    }
}

// ================= K1: routing + count + prefix + scatter (single CTA) =================
__global__ __launch_bounds__(1024) void route_scatter_kernel() {
    __shared__ int s_cnt[E_NUM];
    __shared__ int s_cur[E_NUM];
    const int tid = threadIdx.x;
    if (tid < E_NUM) s_cnt[tid] = 0;
    __syncthreads();

    int ti0[2], ti1[2];
    float tc0[2], tc1[2];
#pragma unroll
    for (int q = 0; q < 2; q++) {
        int t = tid + q * 1024;
        float s[E_NUM];
#pragma unroll
        for (int e = 0; e < E_NUM; e++) s[e] = g_logits[t * E_NUM + e];
        float mx = s[0];
        int i0 = 0;
#pragma unroll
        for (int e = 1; e < E_NUM; e++)
            if (s[e] > mx) { mx = s[e]; i0 = e; }
        float denom = 0.0f;
#pragma unroll
        for (int e = 0; e < E_NUM; e++) {
            float f = fmaxf(fabsf(s[e]), mx);
            if (!((mx - s[e]) / f > 0.02f)) denom += expf(s[e] - mx);
        }
        float w0 = 1.0f / denom;
        float mx2 = -CUDART_INF_F;
        int i1 = 0;
#pragma unroll
        for (int e = 0; e < E_NUM; e++)
            if (e != i0 && s[e] > mx2) { mx2 = s[e]; i1 = e; }
        float denom2 = 0.0f;
#pragma unroll
        for (int e = 0; e < E_NUM; e++) {
            if (e == i0) continue;
            float f = fmaxf(fabsf(s[e]), mx2);
            if (!((mx2 - s[e]) / f > 0.02f)) denom2 += expf(s[e] - mx2);
        }
        float w1v = 1.0f / denom2;
        // bug-faithful combine: only experts 0 and 1 ever get nonzero coefs
        float c0 = (i0 == 0) ? w0 : ((i1 == 0) ? w1v : 0.0f);
        float c1 = (i0 == 1) ? w0 : ((i1 == 1) ? w1v : 0.0f);
        ti0[q] = i0; tc0[q] = c0;
        ti1[q] = i1; tc1[q] = c1;
        if (c0 != 0.0f) atomicAdd(&s_cnt[i0], 1);
        if (c1 != 0.0f) atomicAdd(&s_cnt[i1], 1);
    }
    __syncthreads();
    if (tid == 0) {
        int acc = 0;
        for (int e = 0; e < E_NUM; e++) {
            g_off[e] = acc;
            s_cur[e] = acc;
            g_cnt[e] = s_cnt[e];
            acc += s_cnt[e];
        }
    }
    __syncthreads();
#pragma unroll
    for (int q = 0; q < 2; q++) {
        int t = tid + q * 1024;
        if (tc0[q] != 0.0f) {
            int slot = atomicAdd(&s_cur[ti0[q]], 1);
            g_tok[slot] = t; g_coef[slot] = tc0[q];
        }
        if (tc1[q] != 0.0f) {
            int slot = atomicAdd(&s_cur[ti1[q]], 1);
            g_tok[slot] = t; g_coef[slot] = tc1[q];
        }
    }
}

// ================= GEMM smem layouts =================
#define A_STRIDE 36     // conflict-free frag loads: bank = 4*gid + tg
#define B_STRIDE 136    // conflict-free frag loads: bank = 8*tg + gid
// GEMM1: M=128 tile
#define G1_A_W   (128 * A_STRIDE)   // 4608 words per buf
#define G1_B_W   (32 * B_STRIDE)    // 4352 words per buf
#define G1_A_OFF 512
#define G1_B1_OFF (G1_A_OFF + 2 * G1_A_W * 4)              // 512 + 36864
#define G1_B3_OFF (G1_B1_OFF + 2 * G1_B_W * 4)             // + 34816
#define G1_SMEM   (G1_B3_OFF + 2 * G1_B_W * 4)             // 107008
// GEMM2: M=64 tile
#define G2_A_W   (64 * A_STRIDE)    // 2304 words per buf
#define G2_B_W   (32 * B_STRIDE)
#define G2_A_OFF 512
#define G2_B_OFF (G2_A_OFF + 2 * G2_A_W * 4)               // 512 + 18432
#define G2_SMEM  (G2_B_OFF + 2 * G2_B_W * 4)               // 53760

// ================= GEMM1: h = silu(Xe@W1) * (Xe@W3) =================
// block tile M=128, N=128, Kc=32; 16 warps (4x4), warp tile 32x32 per matrix
__global__ __launch_bounds__(512) void gemm1_kernel(
    const float* __restrict__ x, const float* __restrict__ w1, const float* __restrict__ w3) {
    const int e = blockIdx.z;
    const int cnt = g_cnt[e];
    const int m0 = blockIdx.y * 128;
    if (m0 >= cnt) return;
    const int off = g_off[e];
    const int n0 = blockIdx.x * 128;
    const float* __restrict__ W1 = w1 + (size_t)e * H_DIM * F_DIM;
    const float* __restrict__ W3 = w3 + (size_t)e * H_DIM * F_DIM;

    extern __shared__ char sm[];
    int* stok = (int*)sm;
    float* Abuf  = (float*)(sm + G1_A_OFF);
    float* B1buf = (float*)(sm + G1_B1_OFF);
    float* B3buf = (float*)(sm + G1_B3_OFF);

    const int tid = threadIdx.x, wid = tid >> 5, lane = tid & 31;
    const int gid = lane >> 2, tg = lane & 3;
    const int wm = wid >> 2, wn = wid & 3;

    if (tid < 128) {
        int r = m0 + tid;
        stok[tid] = g_tok[off + (r < cnt ? r : cnt - 1)];
    }
    __syncthreads();

    // per-thread loader slots (fixed across chunks)
    const float* asrc[2];
    uint32_t adst[2];
#pragma unroll
    for (int i = 0; i < 2; i++) {
        int idx = tid + i * 512;
        int row = idx >> 3, c4 = idx & 7;
        asrc[i] = x + (size_t)stok[row] * H_DIM + c4 * 4;
        adst[i] = (uint32_t)(row * A_STRIDE + c4 * 4) * 4;
    }
    const float* b1src[2];
    const float* b3src[2];
    uint32_t bdst[2];
#pragma unroll
    for (int i = 0; i < 2; i++) {
        int idx = tid + i * 512;
        int kk = idx >> 5, f4 = idx & 31;
        b1src[i] = W1 + (size_t)kk * F_DIM + n0 + f4 * 4;
        b3src[i] = W3 + (size_t)kk * F_DIM + n0 + f4 * 4;
        bdst[i] = (uint32_t)(kk * B_STRIDE + f4 * 4) * 4;
    }
    const uint32_t Ab = smem_u32(Abuf), B1b = smem_u32(B1buf), B3b = smem_u32(B3buf);

    float acc1[2][4][4] = {};
    float acc3[2][4][4] = {};

#define G1_ISSUE(c)                                                       \
    do {                                                                  \
        uint32_t _bo = ((c) & 1) ? 1u : 0u;                               \
        size_t _ka = (size_t)(c) * 32;                                    \
        size_t _kb = (size_t)(c) * 32 * F_DIM;                            \
        _Pragma("unroll") for (int _i = 0; _i < 2; _i++)                  \
            CPA(Ab + _bo * (G1_A_W * 4) + adst[_i], asrc[_i] + _ka);      \
        _Pragma("unroll") for (int _i = 0; _i < 2; _i++) {                \
            CPA(B1b + _bo * (G1_B_W * 4) + bdst[_i], b1src[_i] + _kb);    \
            CPA(B3b + _bo * (G1_B_W * 4) + bdst[_i], b3src[_i] + _kb);    \
        }                                                                 \
        CPA_COMMIT();                                                     \
    } while (0)

    G1_ISSUE(0);
    for (int c = 0; c < 32; c++) {
        if (c + 1 < 32) { G1_ISSUE(c + 1); CPA_WAIT1(); }
        else CPA_WAIT0();
        __syncthreads();
        const int b = c & 1;
        const float* A  = Abuf + b * G1_A_W;
        const float* B1 = B1buf + b * G1_B_W;
        const float* B3 = B3buf + b * G1_B_W;
#pragma unroll
        for (int ks = 0; ks < 4; ks++) {
            uint32_t a[2][4];
#pragma unroll
            for (int mt = 0; mt < 2; mt++) {
                int rb = (wm * 32 + mt * 16 + gid) * A_STRIDE + ks * 8 + tg;
                a[mt][0] = f2tf(A[rb]);
                a[mt][1] = f2tf(A[rb + 8 * A_STRIDE]);
                a[mt][2] = f2tf(A[rb + 4]);
                a[mt][3] = f2tf(A[rb + 8 * A_STRIDE + 4]);
            }
#pragma unroll
            for (int nt = 0; nt < 4; nt++) {
                int bb = (ks * 8 + tg) * B_STRIDE + wn * 32 + nt * 8 + gid;
                uint32_t b10 = f2tf(B1[bb]), b11 = f2tf(B1[bb + 4 * B_STRIDE]);
                uint32_t b30 = f2tf(B3[bb]), b31 = f2tf(B3[bb + 4 * B_STRIDE]);
#pragma unroll
                for (int mt = 0; mt < 2; mt++) {
                    MMA_TF32(acc1[mt][nt], a[mt], b10, b11);
                    MMA_TF32(acc3[mt][nt], a[mt], b30, b31);
                }
            }
        }
        __syncthreads();
    }

    // epilogue: silu(acc1)*acc3 -> g_h
#pragma unroll
    for (int mt = 0; mt < 2; mt++) {
#pragma unroll
        for (int half = 0; half < 2; half++) {
            int row = m0 + wm * 32 + mt * 16 + half * 8 + gid;
            if (row < cnt) {
                float* hp = g_h + (size_t)(off + row) * F_DIM + n0 + wn * 32 + tg * 2;
#pragma unroll
                for (int nt = 0; nt < 4; nt++) {
                    float g0 = acc1[mt][nt][half * 2 + 0];
                    float g1 = acc1[mt][nt][half * 2 + 1];
                    float u0 = acc3[mt][nt][half * 2 + 0];
                    float u1 = acc3[mt][nt][half * 2 + 1];
                    float o0 = u0 * (g0 / (1.0f + expf(-g0)));
                    float o1 = u1 * (g1 / (1.0f + expf(-g1)));
                    *(float2*)(hp + nt * 8) = make_float2(o0, o1);
                }
            }
        }
    }
}

// ================= GEMM2: out += coef * (h @ W2) =================
// block tile M=64, N=128, Kc=32, K=4096; 8 warps (2x4), warp tile 32x32
__global__ __launch_bounds__(256) void gemm2_kernel(
    const float* __restrict__ w2, float* __restrict__ out) {
    const int e = blockIdx.z;
    const int cnt = g_cnt[e];
    const int m0 = blockIdx.y * 64;
    if (m0 >= cnt) return;
    const int off = g_off[e];
    const int n0 = blockIdx.x * 128;
    const float* __restrict__ W2 = w2 + (size_t)e * F_DIM * H_DIM;

    extern __shared__ char sm[];
    int* srow = (int*)sm;
    float* Abuf = (float*)(sm + G2_A_OFF);
    float* Bbuf = (float*)(sm + G2_B_OFF);

    const int tid = threadIdx.x, wid = tid >> 5, lane = tid & 31;
    const int gid = lane >> 2, tg = lane & 3;
    const int wm = wid >> 2, wn = wid & 3;

    if (tid < 64) {
        int r = m0 + tid;
        srow[tid] = off + (r < cnt ? r : cnt - 1);
    }
    __syncthreads();

    const float* asrc[2];
    uint32_t adst[2];
#pragma unroll
    for (int i = 0; i < 2; i++) {
        int idx = tid + i * 256;
        int row = idx >> 3, c4 = idx & 7;
        asrc[i] = g_h + (size_t)srow[row] * F_DIM + c4 * 4;
        adst[i] = (uint32_t)(row * A_STRIDE + c4 * 4) * 4;
    }
    const float* bsrc[4];
    uint32_t bdst[4];
#pragma unroll
    for (int i = 0; i < 4; i++) {
        int idx = tid + i * 256;
        int kk = idx >> 5, f4 = idx & 31;
        bsrc[i] = W2 + (size_t)kk * H_DIM + n0 + f4 * 4;
        bdst[i] = (uint32_t)(kk * B_STRIDE + f4 * 4) * 4;
    }
    const uint32_t Ab = smem_u32(Abuf), Bb = smem_u32(Bbuf);

    float acc[2][4][4] = {};

#define G2_ISSUE(c)                                                     \
    do {                                                                \
        uint32_t _bo = ((c) & 1) ? 1u : 0u;                             \
        size_t _ka = (size_t)(c) * 32;                                  \
        size_t _kb = (size_t)(c) * 32 * H_DIM;                          \
        _Pragma("unroll") for (int _i = 0; _i < 2; _i++)                \
            CPA(Ab + _bo * (G2_A_W * 4) + adst[_i], asrc[_i] + _ka);    \
        _Pragma("unroll") for (int _i = 0; _i < 4; _i++)                \
            CPA(Bb + _bo * (G2_B_W * 4) + bdst[_i], bsrc[_i] + _kb);    \
        CPA_COMMIT();                                                   \
    } while (0)

    G2_ISSUE(0);
    for (int c = 0; c < 128; c++) {
        if (c + 1 < 128) { G2_ISSUE(c + 1); CPA_WAIT1(); }
        else CPA_WAIT0();
        __syncthreads();
        const int b = c & 1;
        const float* A = Abuf + b * G2_A_W;
        const float* B = Bbuf + b * G2_B_W;
#pragma unroll
        for (int ks = 0; ks < 4; ks++) {
            uint32_t a[2][4];
#pragma unroll
            for (int mt = 0; mt < 2; mt++) {
                int rb = (wm * 32 + mt * 16 + gid) * A_STRIDE + ks * 8 + tg;
                a[mt][0] = f2tf(A[rb]);
                a[mt][1] = f2tf(A[rb + 8 * A_STRIDE]);
                a[mt][2] = f2tf(A[rb + 4]);
                a[mt][3] = f2tf(A[rb + 8 * A_STRIDE + 4]);
            }
#pragma unroll
            for (int nt = 0; nt < 4; nt++) {
                int bb = (ks * 8 + tg) * B_STRIDE + wn * 32 + nt * 8 + gid;
                uint32_t b0 = f2tf(B[bb]), b1 = f2tf(B[bb + 4 * B_STRIDE]);
#pragma unroll
                for (int mt = 0; mt < 2; mt++) MMA_TF32(acc[mt][nt], a[mt], b0, b1);
            }
        }
        __syncthreads();
    }

    // epilogue: atomic scaled scatter
#pragma unroll
    for (int mt = 0; mt < 2; mt++) {
#pragma unroll
        for (int half = 0; half < 2; half++) {
            int row = m0 + wm * 32 + mt * 16 + half * 8 + gid;
            if (row < cnt) {
                int slot = off + row;
                int tok = g_tok[slot];
                float coef = g_coef[slot];
                float* dst = out + (size_t)tok * H_DIM + n0 + wn * 32 + tg * 2;
#pragma unroll
                for (int nt = 0; nt < 4; nt++) {
                    atomicAdd(dst + nt * 8 + 0, acc[mt][nt][half * 2 + 0] * coef);
                    atomicAdd(dst + nt * 8 + 1, acc[mt][nt][half * 2 + 1] * coef);
                }
            }
        }
    }
}

// ================= launch =================
extern "C" void kernel_launch(void* const* d_in, const int* in_sizes, int n_in,
                              void* d_out, int out_size) {
    const float* x  = (const float*)d_in[0];
    const float* gw = (const float*)d_in[1];
    const float* w1 = (const float*)d_in[2];
    const float* w3 = (const float*)d_in[3];
    const float* w2 = (const float*)d_in[4];
    float* out = (float*)d_out;
    float* out_logits = out + (size_t)T_TOK * H_DIM;

    cudaFuncSetAttribute(gemm1_kernel, cudaFuncAttributeMaxDynamicSharedMemorySize, G1_SMEM);
    cudaFuncSetAttribute(gemm2_kernel, cudaFuncAttributeMaxDynamicSharedMemorySize, G2_SMEM);

    router_kernel<<<T_TOK / 8, 256>>>(x, gw, out, out_logits);
    route_scatter_kernel<<<1, 1024>>>();
    gemm1_kernel<<<dim3(F_DIM / 128, T_TOK / 128, E_NUM), 512, G1_SMEM>>>(x, w1, w3);
    gemm2_kernel<<<dim3(H_DIM / 128, T_TOK / 64, E_NUM), 256, G2_SMEM>>>(w2, out);
}

// round 6
// speedup vs baseline: 5.2109x; 1.2970x over previous
#include <cuda_runtime.h>
#include <cuda_fp16.h>
#include <math.h>
#include <math_constants.h>
#include <cstdint>

#define T_TOK 2048
#define H_DIM 1024
#define F_DIM 4096
#define E_NUM 8
#define MAXPAIRS (2 * T_TOK)

// ================= scratch (__device__ globals; no runtime alloc) =================
__device__ float  g_logits[T_TOK * E_NUM];
__device__ int    g_cnt[E_NUM];
__device__ int    g_off[E_NUM];
__device__ int    g_tok[MAXPAIRS];
__device__ float  g_coef[MAXPAIRS];
__device__ __align__(16) __half g_xh[T_TOK * H_DIM];                      // x in fp16
__device__ __align__(16) __half g_w1t[(size_t)E_NUM * F_DIM * H_DIM];     // W1[e][n][k] fp16
__device__ __align__(16) __half g_w3t[(size_t)E_NUM * F_DIM * H_DIM];     // W3[e][n][k] fp16
__device__ __align__(16) __half g_w2t[(size_t)E_NUM * H_DIM * F_DIM];     // W2[e][n=h][k=f] fp16
__device__ __align__(16) __half g_h16[(size_t)MAXPAIRS * F_DIM];          // intermediate, fp16

// ================= helpers =================
__device__ __forceinline__ uint32_t smem_u32(const void* p) {
    uint32_t a;
    asm("{ .reg .u64 t; cvta.to.shared.u64 t, %1; cvt.u32.u64 %0, t; }" : "=r"(a) : "l"(p));
    return a;
}
#define CPA(dst, src) \
    asm volatile("cp.async.cg.shared.global [%0], [%1], 16;" ::"r"(dst), "l"(src) : "memory")
#define CPA_COMMIT() asm volatile("cp.async.commit_group;" ::: "memory")
#define CPA_WAIT1()  asm volatile("cp.async.wait_group 1;" ::: "memory")
#define CPA_WAIT0()  asm volatile("cp.async.wait_group 0;" ::: "memory")
#define MMA_F16(d, a, b0, b1)                                                            \
    asm volatile(                                                                        \
        "mma.sync.aligned.m16n8k16.row.col.f32.f16.f16.f32 "                             \
        "{%0,%1,%2,%3},{%4,%5,%6,%7},{%8,%9},{%0,%1,%2,%3};"                             \
        : "+f"((d)[0]), "+f"((d)[1]), "+f"((d)[2]), "+f"((d)[3])                         \
        : "r"((a)[0]), "r"((a)[1]), "r"((a)[2]), "r"((a)[3]), "r"(b0), "r"(b1))

// ================= K0: router logits + zero output rows + x->fp16 =================
__global__ __launch_bounds__(256) void router_kernel(
    const float* __restrict__ x, const float* __restrict__ gw,
    float* __restrict__ out, float* __restrict__ out_logits) {
    __shared__ float sgw[E_NUM * H_DIM];
    for (int i = threadIdx.x; i < H_DIM * E_NUM; i += 256) {
        int h = i >> 3, e = i & 7;
        sgw[e * H_DIM + h] = gw[i];
    }
    // zero 8 out rows
    {
        float4 z = make_float4(0.f, 0.f, 0.f, 0.f);
        float4* dst = (float4*)(out + (size_t)blockIdx.x * 8 * H_DIM);
#pragma unroll
        for (int i = 0; i < 8; i++) dst[threadIdx.x + i * 256] = z;
    }
    // convert this CTA's 8 token rows to fp16
    {
        const float4* src = (const float4*)(x + (size_t)blockIdx.x * 8 * H_DIM);
        __half2* dst = (__half2*)(g_xh + (size_t)blockIdx.x * 8 * H_DIM);
#pragma unroll
        for (int i = 0; i < 8; i++) {
            float4 v = src[threadIdx.x + i * 256];
            dst[(threadIdx.x + i * 256) * 2 + 0] = __floats2half2_rn(v.x, v.y);
            dst[(threadIdx.x + i * 256) * 2 + 1] = __floats2half2_rn(v.z, v.w);
        }
    }
    __syncthreads();
    int warp = threadIdx.x >> 5, lane = threadIdx.x & 31;
    int t = blockIdx.x * 8 + warp;
    const float* xr = x + (size_t)t * H_DIM;
    float acc[E_NUM];
#pragma unroll
    for (int e = 0; e < E_NUM; e++) acc[e] = 0.0f;
    for (int h = lane; h < H_DIM; h += 32) {
        float xv = xr[h];
#pragma unroll
        for (int e = 0; e < E_NUM; e++) acc[e] += xv * sgw[e * H_DIM + h];
    }
#pragma unroll
    for (int e = 0; e < E_NUM; e++) {
#pragma unroll
        for (int o = 16; o > 0; o >>= 1) acc[e] += __shfl_down_sync(0xffffffffu, acc[e], o);
    }
    if (lane == 0) {
#pragma unroll
        for (int e = 0; e < E_NUM; e++) {
            g_logits[t * E_NUM + e] = acc[e];
            out_logits[t * E_NUM + e] = acc[e];
        }
    }
}

// ================= K1: weight transpose + fp16 convert (ALL 8 experts) =================
// z = m*8 + e ; m: 0->w1, 1->w3 (R=H,C=F) ; 2->w2 (R=F,C=H). dst[C][R] = (half)src[R][C]
__global__ __launch_bounds__(256) void convert_w_kernel(
    const float* __restrict__ w1, const float* __restrict__ w3, const float* __restrict__ w2) {
    const int z = blockIdx.z;
    const int e = z & 7, m = z >> 3;
    const float* src;
    __half* dst;
    int R, C;
    if (m == 0)      { src = w1 + (size_t)e * H_DIM * F_DIM; dst = g_w1t + (size_t)e * F_DIM * H_DIM; R = H_DIM; C = F_DIM; }
    else if (m == 1) { src = w3 + (size_t)e * H_DIM * F_DIM; dst = g_w3t + (size_t)e * F_DIM * H_DIM; R = H_DIM; C = F_DIM; }
    else             { src = w2 + (size_t)e * F_DIM * H_DIM; dst = g_w2t + (size_t)e * H_DIM * F_DIM; R = F_DIM; C = H_DIM; }
    int rt, ct;
    if (R == H_DIM) { rt = blockIdx.y; ct = blockIdx.x; }                              // 32 x 128 tiles
    else            { rt = blockIdx.y * 4 + (blockIdx.x >> 5); ct = blockIdx.x & 31; } // 128 x 32
    const int r0 = rt * 32, c0 = ct * 32;
    __shared__ float t[32][33];
    const int tx = threadIdx.x & 31, ty = threadIdx.x >> 5;
#pragma unroll
    for (int i = 0; i < 4; i++)
        t[ty + i * 8][tx] = src[(size_t)(r0 + ty + i * 8) * C + c0 + tx];
    __syncthreads();
#pragma unroll
    for (int i = 0; i < 4; i++)
        dst[(size_t)(c0 + ty + i * 8) * R + r0 + tx] = __float2half(t[tx][ty + i * 8]);
}

// ================= K2: routing + count + prefix + scatter (single CTA) =================
__global__ __launch_bounds__(1024) void route_scatter_kernel() {
    __shared__ int s_cnt[E_NUM];
    __shared__ int s_cur[E_NUM];
    const int tid = threadIdx.x;
    if (tid < E_NUM) s_cnt[tid] = 0;
    __syncthreads();
    int ti0[2], ti1[2];
    float tc0[2], tc1[2];
#pragma unroll
    for (int q = 0; q < 2; q++) {
        int t = tid + q * 1024;
        float s[E_NUM];
#pragma unroll
        for (int e = 0; e < E_NUM; e++) s[e] = g_logits[t * E_NUM + e];
        float mx = s[0];
        int i0 = 0;
#pragma unroll
        for (int e = 1; e < E_NUM; e++)
            if (s[e] > mx) { mx = s[e]; i0 = e; }
        float denom = 0.0f;
#pragma unroll
        for (int e = 0; e < E_NUM; e++) {
            float f = fmaxf(fabsf(s[e]), mx);
            if (!((mx - s[e]) / f > 0.02f)) denom += expf(s[e] - mx);
        }
        float w0 = 1.0f / denom;
        float mx2 = -CUDART_INF_F;
        int i1 = 0;
#pragma unroll
        for (int e = 0; e < E_NUM; e++)
            if (e != i0 && s[e] > mx2) { mx2 = s[e]; i1 = e; }
        float denom2 = 0.0f;
#pragma unroll
        for (int e = 0; e < E_NUM; e++) {
            if (e == i0) continue;
            float f = fmaxf(fabsf(s[e]), mx2);
            if (!((mx2 - s[e]) / f > 0.02f)) denom2 += expf(s[e] - mx2);
        }
        float w1v = 1.0f / denom2;
        // dense-table quirk: pair (i0, c0) and (i1, c1); any expert can appear
        float c0 = (i0 == 0) ? w0 : ((i1 == 0) ? w1v : 0.0f);
        float c1 = (i0 == 1) ? w0 : ((i1 == 1) ? w1v : 0.0f);
        ti0[q] = i0; tc0[q] = c0;
        ti1[q] = i1; tc1[q] = c1;
        if (c0 != 0.0f) atomicAdd(&s_cnt[i0], 1);
        if (c1 != 0.0f) atomicAdd(&s_cnt[i1], 1);
    }
    __syncthreads();
    if (tid == 0) {
        int acc = 0;
        for (int e = 0; e < E_NUM; e++) {
            g_off[e] = acc;
            s_cur[e] = acc;
            g_cnt[e] = s_cnt[e];
            acc += s_cnt[e];
        }
    }
    __syncthreads();
#pragma unroll
    for (int q = 0; q < 2; q++) {
        int t = tid + q * 1024;
        if (tc0[q] != 0.0f) {
            int slot = atomicAdd(&s_cur[ti0[q]], 1);
            g_tok[slot] = t; g_coef[slot] = tc0[q];
        }
        if (tc1[q] != 0.0f) {
            int slot = atomicAdd(&s_cur[ti1[q]], 1);
            g_tok[slot] = t; g_coef[slot] = tc1[q];
        }
    }
}

// ================= GEMM smem layouts (fp16, row stride 40 halves = 20 words) =================
#define TW 20
#define G1_A_W   (128 * TW)
#define G1_B_W   (128 * TW)
#define G1_A_OFF 512
#define G1_B1_OFF (G1_A_OFF + 2 * G1_A_W * 4)
#define G1_B3_OFF (G1_B1_OFF + 2 * G1_B_W * 4)
#define G1_SMEM   (G1_B3_OFF + 2 * G1_B_W * 4)     // 61952
#define G2_A_W   (64 * TW)
#define G2_B_W   (128 * TW)
#define G2_A_OFF 512
#define G2_B_OFF (G2_A_OFF + 2 * G2_A_W * 4)
#define G2_SMEM  (G2_B_OFF + 2 * G2_B_W * 4)       // 31232

// ================= GEMM1: h = silu(Xe@W1) * (Xe@W3)  (fp16 MMA) =================
// tile M=128, N=128, Kc=32; 16 warps (4x4), warp tile 32x32 per matrix
__global__ __launch_bounds__(512) void gemm1_kernel() {
    const int e = blockIdx.z;
    const int cnt = g_cnt[e];
    const int m0 = blockIdx.y * 128;
    if (m0 >= cnt) return;
    const int off = g_off[e];
    const int n0 = blockIdx.x * 128;
    const __half* __restrict__ W1 = g_w1t + (size_t)e * F_DIM * H_DIM;
    const __half* __restrict__ W3 = g_w3t + (size_t)e * F_DIM * H_DIM;

    extern __shared__ char sm[];
    int* stok = (int*)sm;
    uint32_t* Abuf  = (uint32_t*)(sm + G1_A_OFF);
    uint32_t* B1buf = (uint32_t*)(sm + G1_B1_OFF);
    uint32_t* B3buf = (uint32_t*)(sm + G1_B3_OFF);

    const int tid = threadIdx.x, wid = tid >> 5, lane = tid & 31;
    const int gid = lane >> 2, tg = lane & 3;
    const int wm = wid >> 2, wn = wid & 3;

    if (tid < 128) {
        int r = m0 + tid;
        stok[tid] = g_tok[off + (r < cnt ? r : cnt - 1)];
    }
    __syncthreads();

    const int lrow = tid >> 2, lc = tid & 3;
    const __half* asrc = g_xh + (size_t)stok[lrow] * H_DIM + lc * 8;
    const __half* b1s  = W1 + (size_t)(n0 + lrow) * H_DIM + lc * 8;
    const __half* b3s  = W3 + (size_t)(n0 + lrow) * H_DIM + lc * 8;
    const uint32_t ldst = (uint32_t)(lrow * 80 + lc * 16);
    const uint32_t Ab = smem_u32(Abuf), B1b = smem_u32(B1buf), B3b = smem_u32(B3buf);

    float acc1[2][4][4] = {};
    float acc3[2][4][4] = {};

#define G1_ISSUE(c)                                               \
    do {                                                          \
        uint32_t _bo = ((c) & 1) * (G1_A_W * 4);                  \
        size_t _k = (size_t)(c) * 32;                             \
        CPA(Ab + _bo + ldst, asrc + _k);                          \
        CPA(B1b + _bo + ldst, b1s + _k);                          \
        CPA(B3b + _bo + ldst, b3s + _k);                          \
        CPA_COMMIT();                                             \
    } while (0)

    G1_ISSUE(0);
    for (int c = 0; c < 32; c++) {
        if (c + 1 < 32) { G1_ISSUE(c + 1); CPA_WAIT1(); }
        else CPA_WAIT0();
        __syncthreads();
        const int b = c & 1;
        const uint32_t* A  = Abuf + b * G1_A_W;
        const uint32_t* B1 = B1buf + b * G1_B_W;
        const uint32_t* B3 = B3buf + b * G1_B_W;
#pragma unroll
        for (int ks = 0; ks < 2; ks++) {
            uint32_t a[2][4];
#pragma unroll
            for (int mt = 0; mt < 2; mt++) {
                int rb = (wm * 32 + mt * 16 + gid) * TW + tg + ks * 8;
                a[mt][0] = A[rb];
                a[mt][1] = A[rb + 8 * TW];
                a[mt][2] = A[rb + 4];
                a[mt][3] = A[rb + 8 * TW + 4];
            }
#pragma unroll
            for (int nt = 0; nt < 4; nt++) {
                int bb = (wn * 32 + nt * 8 + gid) * TW + tg + ks * 8;
                uint32_t b10 = B1[bb], b11 = B1[bb + 4];
                uint32_t b30 = B3[bb], b31 = B3[bb + 4];
#pragma unroll
                for (int mt = 0; mt < 2; mt++) {
                    MMA_F16(acc1[mt][nt], a[mt], b10, b11);
                    MMA_F16(acc3[mt][nt], a[mt], b30, b31);
                }
            }
        }
        __syncthreads();
    }

    // epilogue: silu(acc1)*acc3 -> g_h16 (fp16)
#pragma unroll
    for (int mt = 0; mt < 2; mt++) {
#pragma unroll
        for (int half = 0; half < 2; half++) {
            int row = m0 + wm * 32 + mt * 16 + half * 8 + gid;
            if (row < cnt) {
                __half* hp = g_h16 + (size_t)(off + row) * F_DIM + n0 + wn * 32 + tg * 2;
#pragma unroll
                for (int nt = 0; nt < 4; nt++) {
                    float g0 = acc1[mt][nt][half * 2 + 0];
                    float g1 = acc1[mt][nt][half * 2 + 1];
                    float u0 = acc3[mt][nt][half * 2 + 0];
                    float u1 = acc3[mt][nt][half * 2 + 1];
                    float o0 = u0 * (g0 / (1.0f + expf(-g0)));
                    float o1 = u1 * (g1 / (1.0f + expf(-g1)));
                    *(__half2*)(hp + nt * 8) = __floats2half2_rn(o0, o1);
                }
            }
        }
    }
}

// ================= GEMM2: out += coef * (h @ W2)  (fp16 MMA, split-K 4) =================
// tile M=64, N=128, Ksplit=1024, Kc=32; 8 warps (2x4), warp tile 32x32
__global__ __launch_bounds__(256) void gemm2_kernel(float* __restrict__ out) {
    const int z = blockIdx.z;
    const int e = z >> 2, ks4 = z & 3;
    const int cnt = g_cnt[e];
    const int m0 = blockIdx.y * 64;
    if (m0 >= cnt) return;
    const int off = g_off[e];
    const int n0 = blockIdx.x * 128;
    const int kbase = ks4 * (F_DIM / 4);
    const __half* __restrict__ W2 = g_w2t + (size_t)e * H_DIM * F_DIM;

    extern __shared__ char sm[];
    int* srow = (int*)sm;
    uint32_t* Abuf = (uint32_t*)(sm + G2_A_OFF);
    uint32_t* Bbuf = (uint32_t*)(sm + G2_B_OFF);

    const int tid = threadIdx.x, wid = tid >> 5, lane = tid & 31;
    const int gid = lane >> 2, tg = lane & 3;
    const int wm = wid >> 2, wn = wid & 3;

    if (tid < 64) {
        int r = m0 + tid;
        srow[tid] = off + (r < cnt ? r : cnt - 1);
    }
    __syncthreads();

    const int arow = tid >> 2, ac = tid & 3;
    const __half* asrc = g_h16 + (size_t)srow[arow] * F_DIM + kbase + ac * 8;
    const uint32_t adst = (uint32_t)(arow * 80 + ac * 16);
    const __half* bsrc[2];
    uint32_t bdst[2];
#pragma unroll
    for (int i = 0; i < 2; i++) {
        int idx = tid + i * 256;
        int n = idx >> 2, c = idx & 3;
        bsrc[i] = W2 + (size_t)(n0 + n) * F_DIM + kbase + c * 8;
        bdst[i] = (uint32_t)(n * 80 + c * 16);
    }
    const uint32_t Ab = smem_u32(Abuf), Bb = smem_u32(Bbuf);

    float acc[2][4][4] = {};

#define G2_ISSUE(c)                                               \
    do {                                                          \
        uint32_t _ao = ((c) & 1) * (G2_A_W * 4);                  \
        uint32_t _bo = ((c) & 1) * (G2_B_W * 4);                  \
        size_t _k = (size_t)(c) * 32;                             \
        CPA(Ab + _ao + adst, asrc + _k);                          \
        CPA(Bb + _bo + bdst[0], bsrc[0] + _k);                    \
        CPA(Bb + _bo + bdst[1], bsrc[1] + _k);                    \
        CPA_COMMIT();                                             \
    } while (0)

    G2_ISSUE(0);
    for (int c = 0; c < 32; c++) {
        if (c + 1 < 32) { G2_ISSUE(c + 1); CPA_WAIT1(); }
        else CPA_WAIT0();
        __syncthreads();
        const int b = c & 1;
        const uint32_t* A = Abuf + b * G2_A_W;
        const uint32_t* B = Bbuf + b * G2_B_W;
#pragma unroll
        for (int ks = 0; ks < 2; ks++) {
            uint32_t a[2][4];
#pragma unroll
            for (int mt = 0; mt < 2; mt++) {
                int rb = (wm * 32 + mt * 16 + gid) * TW + tg + ks * 8;
                a[mt][0] = A[rb];
                a[mt][1] = A[rb + 8 * TW];
                a[mt][2] = A[rb + 4];
                a[mt][3] = A[rb + 8 * TW + 4];
            }
#pragma unroll
            for (int nt = 0; nt < 4; nt++) {
                int bb = (wn * 32 + nt * 8 + gid) * TW + tg + ks * 8;
                uint32_t b0 = B[bb], b1 = B[bb + 4];
#pragma unroll
                for (int mt = 0; mt < 2; mt++) MMA_F16(acc[mt][nt], a[mt], b0, b1);
            }
        }
        __syncthreads();
    }

    // epilogue: atomic scaled scatter
#pragma unroll
    for (int mt = 0; mt < 2; mt++) {
#pragma unroll
        for (int half = 0; half < 2; half++) {
            int row = m0 + wm * 32 + mt * 16 + half * 8 + gid;
            if (row < cnt) {
                int slot = off + row;
                int tok = g_tok[slot];
                float coef = g_coef[slot];
                float* dst = out + (size_t)tok * H_DIM + n0 + wn * 32 + tg * 2;
#pragma unroll
                for (int nt = 0; nt < 4; nt++) {
                    atomicAdd(dst + nt * 8 + 0, acc[mt][nt][half * 2 + 0] * coef);
                    atomicAdd(dst + nt * 8 + 1, acc[mt][nt][half * 2 + 1] * coef);
                }
            }
        }
    }
}

// ================= launch =================
extern "C" void kernel_launch(void* const* d_in, const int* in_sizes, int n_in,
                              void* d_out, int out_size) {
    const float* x  = (const float*)d_in[0];
    const float* gw = (const float*)d_in[1];
    const float* w1 = (const float*)d_in[2];
    const float* w3 = (const float*)d_in[3];
    const float* w2 = (const float*)d_in[4];
    float* out = (float*)d_out;
    float* out_logits = out + (size_t)T_TOK * H_DIM;

    cudaFuncSetAttribute(gemm1_kernel, cudaFuncAttributeMaxDynamicSharedMemorySize, G1_SMEM);
    cudaFuncSetAttribute(gemm2_kernel, cudaFuncAttributeMaxDynamicSharedMemorySize, G2_SMEM);

    router_kernel<<<T_TOK / 8, 256>>>(x, gw, out, out_logits);
    convert_w_kernel<<<dim3(128, 32, 24), 256>>>(w1, w3, w2);
    route_scatter_kernel<<<1, 1024>>>();
    gemm1_kernel<<<dim3(F_DIM / 128, T_TOK / 128, E_NUM), 512, G1_SMEM>>>();
    gemm2_kernel<<<dim3(H_DIM / 128, T_TOK / 64, E_NUM * 4), 256, G2_SMEM>>>(out);
}

// round 7
// speedup vs baseline: 6.8663x; 1.3177x over previous
#include <cuda_runtime.h>
#include <cuda_fp16.h>
#include <math.h>
#include <math_constants.h>
#include <cstdint>

#define T_TOK 2048
#define H_DIM 1024
#define F_DIM 4096
#define E_NUM 8
#define MAXPAIRS (2 * T_TOK)

// ================= scratch (__device__ globals; no runtime alloc) =================
__device__ float  g_logits[T_TOK * E_NUM];
__device__ int    g_cnt[E_NUM];
__device__ int    g_off[E_NUM];
__device__ int    g_tok[MAXPAIRS];
__device__ float  g_coef[MAXPAIRS];
__device__ __align__(16) __half g_xh[T_TOK * H_DIM];                 // x in fp16
__device__ __align__(16) __half g_h16[(size_t)MAXPAIRS * F_DIM];     // intermediate, fp16

// ================= helpers =================
__device__ __forceinline__ uint32_t smem_u32(const void* p) {
    uint32_t a;
    asm("{ .reg .u64 t; cvta.to.shared.u64 t, %1; cvt.u32.u64 %0, t; }" : "=r"(a) : "l"(p));
    return a;
}
__device__ __forceinline__ uint32_t h2u(float a, float b) {
    __half2 h = __floats2half2_rn(a, b);
    return *reinterpret_cast<uint32_t*>(&h);
}
#define CPA(dst, src) \
    asm volatile("cp.async.cg.shared.global [%0], [%1], 16;" ::"r"(dst), "l"(src) : "memory")
#define CPA_COMMIT() asm volatile("cp.async.commit_group;" ::: "memory")
#define CPA_WAIT0()  asm volatile("cp.async.wait_group 0;" ::: "memory")
#define MMA_F16(d, a, b0, b1)                                                            \
    asm volatile(                                                                        \
        "mma.sync.aligned.m16n8k16.row.col.f32.f16.f16.f32 "                             \
        "{%0,%1,%2,%3},{%4,%5,%6,%7},{%8,%9},{%0,%1,%2,%3};"                             \
        : "+f"((d)[0]), "+f"((d)[1]), "+f"((d)[2]), "+f"((d)[3])                         \
        : "r"((a)[0]), "r"((a)[1]), "r"((a)[2]), "r"((a)[3]), "r"(b0), "r"(b1))

// transpose-convert one 32k x 128n fp32 chunk (raw[k][n], row=128 floats) into
// fp16 [n][k] tile with row stride 20 words. 512 threads. Bank-conflict-free.
__device__ __forceinline__ void cvt_tile(const float* __restrict__ raw,
                                         uint32_t* __restrict__ conv, int tid) {
    const int n = tid & 127, kg = tid >> 7;          // kg in 0..3, 8 k's each
    const float* src = raw + kg * 8 * 128 + n;
    float f0 = src[0],       f1 = src[128],     f2 = src[2 * 128], f3 = src[3 * 128];
    float f4 = src[4 * 128], f5 = src[5 * 128], f6 = src[6 * 128], f7 = src[7 * 128];
    uint4 p;
    p.x = h2u(f0, f1); p.y = h2u(f2, f3); p.z = h2u(f4, f5); p.w = h2u(f6, f7);
    *(uint4*)(conv + n * 20 + kg * 4) = p;
}

// ================= K0: router logits + zero output rows + x->fp16 =================
__global__ __launch_bounds__(256) void router_kernel(
    const float* __restrict__ x, const float* __restrict__ gw,
    float* __restrict__ out, float* __restrict__ out_logits) {
    __shared__ float sgw[E_NUM * H_DIM];
    for (int i = threadIdx.x; i < H_DIM * E_NUM; i += 256) {
        int h = i >> 3, e = i & 7;
        sgw[e * H_DIM + h] = gw[i];
    }
    {
        float4 z = make_float4(0.f, 0.f, 0.f, 0.f);
        float4* dst = (float4*)(out + (size_t)blockIdx.x * 8 * H_DIM);
#pragma unroll
        for (int i = 0; i < 8; i++) dst[threadIdx.x + i * 256] = z;
    }
    {
        const float4* src = (const float4*)(x + (size_t)blockIdx.x * 8 * H_DIM);
        __half2* dst = (__half2*)(g_xh + (size_t)blockIdx.x * 8 * H_DIM);
#pragma unroll
        for (int i = 0; i < 8; i++) {
            float4 v = src[threadIdx.x + i * 256];
            dst[(threadIdx.x + i * 256) * 2 + 0] = __floats2half2_rn(v.x, v.y);
            dst[(threadIdx.x + i * 256) * 2 + 1] = __floats2half2_rn(v.z, v.w);
        }
    }
    __syncthreads();
    int warp = threadIdx.x >> 5, lane = threadIdx.x & 31;
    int t = blockIdx.x * 8 + warp;
    const float* xr = x + (size_t)t * H_DIM;
    float acc[E_NUM];
#pragma unroll
    for (int e = 0; e < E_NUM; e++) acc[e] = 0.0f;
    for (int h = lane; h < H_DIM; h += 32) {
        float xv = xr[h];
#pragma unroll
        for (int e = 0; e < E_NUM; e++) acc[e] += xv * sgw[e * H_DIM + h];
    }
#pragma unroll
    for (int e = 0; e < E_NUM; e++) {
#pragma unroll
        for (int o = 16; o > 0; o >>= 1) acc[e] += __shfl_down_sync(0xffffffffu, acc[e], o);
    }
    if (lane == 0) {
#pragma unroll
        for (int e = 0; e < E_NUM; e++) {
            g_logits[t * E_NUM + e] = acc[e];
            out_logits[t * E_NUM + e] = acc[e];
        }
    }
}

// ================= K1: routing + count + prefix + scatter (single CTA) =================
__global__ __launch_bounds__(1024) void route_scatter_kernel() {
    __shared__ int s_cnt[E_NUM];
    __shared__ int s_cur[E_NUM];
    const int tid = threadIdx.x;
    if (tid < E_NUM) s_cnt[tid] = 0;
    __syncthreads();
    int ti0[2], ti1[2];
    float tc0[2], tc1[2];
#pragma unroll
    for (int q = 0; q < 2; q++) {
        int t = tid + q * 1024;
        float s[E_NUM];
#pragma unroll
        for (int e = 0; e < E_NUM; e++) s[e] = g_logits[t * E_NUM + e];
        float mx = s[0];
        int i0 = 0;
#pragma unroll
        for (int e = 1; e < E_NUM; e++)
            if (s[e] > mx) { mx = s[e]; i0 = e; }
        float denom = 0.0f;
#pragma unroll
        for (int e = 0; e < E_NUM; e++) {
            float f = fmaxf(fabsf(s[e]), mx);
            if (!((mx - s[e]) / f > 0.02f)) denom += expf(s[e] - mx);
        }
        float w0 = 1.0f / denom;
        float mx2 = -CUDART_INF_F;
        int i1 = 0;
#pragma unroll
        for (int e = 0; e < E_NUM; e++)
            if (e != i0 && s[e] > mx2) { mx2 = s[e]; i1 = e; }
        float denom2 = 0.0f;
#pragma unroll
        for (int e = 0; e < E_NUM; e++) {
            if (e == i0) continue;
            float f = fmaxf(fabsf(s[e]), mx2);
            if (!((mx2 - s[e]) / f > 0.02f)) denom2 += expf(s[e] - mx2);
        }
        float w1v = 1.0f / denom2;
        float c0 = (i0 == 0) ? w0 : ((i1 == 0) ? w1v : 0.0f);
        float c1 = (i0 == 1) ? w0 : ((i1 == 1) ? w1v : 0.0f);
        ti0[q] = i0; tc0[q] = c0;
        ti1[q] = i1; tc1[q] = c1;
        if (c0 != 0.0f) atomicAdd(&s_cnt[i0], 1);
        if (c1 != 0.0f) atomicAdd(&s_cnt[i1], 1);
    }
    __syncthreads();
    if (tid == 0) {
        int acc = 0;
        for (int e = 0; e < E_NUM; e++) {
            g_off[e] = acc;
            s_cur[e] = acc;
            g_cnt[e] = s_cnt[e];
            acc += s_cnt[e];
        }
    }
    __syncthreads();
#pragma unroll
    for (int q = 0; q < 2; q++) {
        int t = tid + q * 1024;
        if (tc0[q] != 0.0f) {
            int slot = atomicAdd(&s_cur[ti0[q]], 1);
            g_tok[slot] = t; g_coef[slot] = tc0[q];
        }
        if (tc1[q] != 0.0f) {
            int slot = atomicAdd(&s_cur[ti1[q]], 1);
            g_tok[slot] = t; g_coef[slot] = tc1[q];
        }
    }
}

// ================= smem layouts =================
// A tile: 128 rows x 32 halves, row stride 80B (TW=20 words), double buffered.
// conv B tile: 128 n x 32 k halves, stride 80B, single buffered.
// raw B chunk: 32 k x 128 n fp32 (row=512B), double buffered.
#define TW 20
// gemm1 (A + B1 + B3)
#define G1_TOK   0
#define G1_SA    512
#define G1_CV1   (G1_SA + 2 * 10240)      // 20992
#define G1_CV3   (G1_CV1 + 10240)         // 31232
#define G1_R1    (G1_CV3 + 10240)         // 41472
#define G1_R3    (G1_R1 + 2 * 16384)      // 74240
#define G1_SMEM  (G1_R3 + 2 * 16384)      // 107008
// gemm2 (A + B)
#define G2_ROW   0
#define G2_SA    512
#define G2_CV    (G2_SA + 2 * 10240)      // 20992
#define G2_R     (G2_CV + 10240)          // 31232
#define G2_SMEM  (G2_R + 2 * 16384)       // 64000

// ================= GEMM1: h = silu(Xe@W1) * (Xe@W3) =================
// tile M=128, N=128, Kc=32; 512 threads (4x4 warps, 32x32 warp tiles).
// Weights read as fp32 [k][n], converted in-smem per chunk.
__global__ __launch_bounds__(512) void gemm1_kernel(
    const float* __restrict__ w1, const float* __restrict__ w3) {
    const int e = blockIdx.z;
    const int cnt = g_cnt[e];
    const int m0 = blockIdx.y * 128;
    if (m0 >= cnt) return;
    const int off = g_off[e];
    const int n0 = blockIdx.x * 128;
    const float* __restrict__ W1 = w1 + (size_t)e * H_DIM * F_DIM;
    const float* __restrict__ W3 = w3 + (size_t)e * H_DIM * F_DIM;

    extern __shared__ char sm[];
    int* stok = (int*)(sm + G1_TOK);
    uint32_t* SA  = (uint32_t*)(sm + G1_SA);
    uint32_t* CV1 = (uint32_t*)(sm + G1_CV1);
    uint32_t* CV3 = (uint32_t*)(sm + G1_CV3);
    float* R1 = (float*)(sm + G1_R1);
    float* R3 = (float*)(sm + G1_R3);

    const int tid = threadIdx.x, wid = tid >> 5, lane = tid & 31;
    const int gid = lane >> 2, tg = lane & 3;
    const int wm = wid >> 2, wn = wid & 3;

    if (tid < 128) {
        int r = m0 + tid;
        stok[tid] = g_tok[off + (r < cnt ? r : cnt - 1)];
    }
    __syncthreads();

    // loader slots
    const int lrow = tid >> 2, lc = tid & 3;                 // A: 128 rows x 4 chunks
    const __half* asrc = g_xh + (size_t)stok[lrow] * H_DIM + lc * 8;
    const uint32_t adst = (uint32_t)(lrow * 80 + lc * 16);
    const int kk0 = tid >> 5, nc0 = tid & 31;                // raw B: idx j*512+tid
    const int kk1 = (tid + 512) >> 5, nc1 = tid & 31;
    const float* b1s0 = W1 + (size_t)kk0 * F_DIM + n0 + nc0 * 4;
    const float* b1s1 = W1 + (size_t)kk1 * F_DIM + n0 + nc1 * 4;
    const float* b3s0 = W3 + (size_t)kk0 * F_DIM + n0 + nc0 * 4;
    const float* b3s1 = W3 + (size_t)kk1 * F_DIM + n0 + nc1 * 4;
    const uint32_t bd0 = (uint32_t)((kk0 * 128 + nc0 * 4) * 4);
    const uint32_t bd1 = (uint32_t)((kk1 * 128 + nc1 * 4) * 4);
    const uint32_t Ab = smem_u32(SA), R1b = smem_u32(R1), R3b = smem_u32(R3);

    float acc1[2][4][4] = {};
    float acc3[2][4][4] = {};

#define G1_ISSUE(c)                                         \
    do {                                                    \
        uint32_t _ao = ((c) & 1) * 10240u;                  \
        uint32_t _ro = ((c) & 1) * 16384u;                  \
        size_t _ka = (size_t)(c) * 32;                      \
        size_t _kb = (size_t)(c) * 32 * F_DIM;              \
        CPA(Ab + _ao + adst, asrc + _ka);                   \
        CPA(R1b + _ro + bd0, b1s0 + _kb);                   \
        CPA(R1b + _ro + bd1, b1s1 + _kb);                   \
        CPA(R3b + _ro + bd0, b3s0 + _kb);                   \
        CPA(R3b + _ro + bd1, b3s1 + _kb);                   \
        CPA_COMMIT();                                       \
    } while (0)

    G1_ISSUE(0);
    for (int c = 0; c < 32; c++) {
        const int b = c & 1;
        CPA_WAIT0();
        __syncthreads();                 // raw(c)/A(c) ready; prior frag reads done
        if (c + 1 < 32) G1_ISSUE(c + 1);
        cvt_tile(R1 + b * 4096, CV1, tid);
        cvt_tile(R3 + b * 4096, CV3, tid);
        __syncthreads();                 // conv ready
        const uint32_t* A = SA + b * 2560;
#pragma unroll
        for (int ks = 0; ks < 2; ks++) {
            uint32_t a[2][4];
#pragma unroll
            for (int mt = 0; mt < 2; mt++) {
                int rb = (wm * 32 + mt * 16 + gid) * TW + tg + ks * 8;
                a[mt][0] = A[rb];
                a[mt][1] = A[rb + 8 * TW];
                a[mt][2] = A[rb + 4];
                a[mt][3] = A[rb + 8 * TW + 4];
            }
#pragma unroll
            for (int nt = 0; nt < 4; nt++) {
                int bb = (wn * 32 + nt * 8 + gid) * TW + tg + ks * 8;
                uint32_t b10 = CV1[bb], b11 = CV1[bb + 4];
                uint32_t b30 = CV3[bb], b31 = CV3[bb + 4];
#pragma unroll
                for (int mt = 0; mt < 2; mt++) {
                    MMA_F16(acc1[mt][nt], a[mt], b10, b11);
                    MMA_F16(acc3[mt][nt], a[mt], b30, b31);
                }
            }
        }
        __syncthreads();                 // done with conv before next overwrite
    }

    // epilogue: silu(acc1)*acc3 -> g_h16 (fp16)
#pragma unroll
    for (int mt = 0; mt < 2; mt++) {
#pragma unroll
        for (int half = 0; half < 2; half++) {
            int row = m0 + wm * 32 + mt * 16 + half * 8 + gid;
            if (row < cnt) {
                __half* hp = g_h16 + (size_t)(off + row) * F_DIM + n0 + wn * 32 + tg * 2;
#pragma unroll
                for (int nt = 0; nt < 4; nt++) {
                    float g0 = acc1[mt][nt][half * 2 + 0];
                    float g1 = acc1[mt][nt][half * 2 + 1];
                    float u0 = acc3[mt][nt][half * 2 + 0];
                    float u1 = acc3[mt][nt][half * 2 + 1];
                    float o0 = u0 * (g0 / (1.0f + expf(-g0)));
                    float o1 = u1 * (g1 / (1.0f + expf(-g1)));
                    *(__half2*)(hp + nt * 8) = __floats2half2_rn(o0, o1);
                }
            }
        }
    }
}

// ================= GEMM2: out += coef * (h @ W2)  (split-K 4) =================
// tile M=128, N=128, Kc=32; 512 threads. W2 read as fp32 [k=f][n=h], converted in-smem.
__global__ __launch_bounds__(512) void gemm2_kernel(
    const float* __restrict__ w2, float* __restrict__ out) {
    const int z = blockIdx.z;
    const int e = z >> 2, ks4 = z & 3;
    const int cnt = g_cnt[e];
    const int m0 = blockIdx.y * 128;
    if (m0 >= cnt) return;
    const int off = g_off[e];
    const int n0 = blockIdx.x * 128;
    const int kbase = ks4 * (F_DIM / 4);
    const float* __restrict__ W2 = w2 + (size_t)e * F_DIM * H_DIM;

    extern __shared__ char sm[];
    int* srow = (int*)(sm + G2_ROW);
    uint32_t* SA = (uint32_t*)(sm + G2_SA);
    uint32_t* CV = (uint32_t*)(sm + G2_CV);
    float* RB = (float*)(sm + G2_R);

    const int tid = threadIdx.x, wid = tid >> 5, lane = tid & 31;
    const int gid = lane >> 2, tg = lane & 3;
    const int wm = wid >> 2, wn = wid & 3;

    if (tid < 128) {
        int r = m0 + tid;
        srow[tid] = off + (r < cnt ? r : cnt - 1);
    }
    __syncthreads();

    const int lrow = tid >> 2, lc = tid & 3;
    const __half* asrc = g_h16 + (size_t)srow[lrow] * F_DIM + kbase + lc * 8;
    const uint32_t adst = (uint32_t)(lrow * 80 + lc * 16);
    const int kk0 = tid >> 5, nc0 = tid & 31;
    const int kk1 = (tid + 512) >> 5, nc1 = tid & 31;
    const float* bs0 = W2 + (size_t)(kbase + kk0) * H_DIM + n0 + nc0 * 4;
    const float* bs1 = W2 + (size_t)(kbase + kk1) * H_DIM + n0 + nc1 * 4;
    const uint32_t bd0 = (uint32_t)((kk0 * 128 + nc0 * 4) * 4);
    const uint32_t bd1 = (uint32_t)((kk1 * 128 + nc1 * 4) * 4);
    const uint32_t Ab = smem_u32(SA), Rb = smem_u32(RB);

    float acc[2][4][4] = {};

#define G2_ISSUE(c)                                         \
    do {                                                    \
        uint32_t _ao = ((c) & 1) * 10240u;                  \
        uint32_t _ro = ((c) & 1) * 16384u;                  \
        size_t _ka = (size_t)(c) * 32;                      \
        size_t _kb = (size_t)(c) * 32 * H_DIM;              \
        CPA(Ab + _ao + adst, asrc + _ka);                   \
        CPA(Rb + _ro + bd0, bs0 + _kb);                     \
        CPA(Rb + _ro + bd1, bs1 + _kb);                     \
        CPA_COMMIT();                                       \
    } while (0)

    G2_ISSUE(0);
    for (int c = 0; c < 32; c++) {
        const int b = c & 1;
        CPA_WAIT0();
        __syncthreads();
        if (c + 1 < 32) G2_ISSUE(c + 1);
        cvt_tile(RB + b * 4096, CV, tid);
        __syncthreads();
        const uint32_t* A = SA + b * 2560;
#pragma unroll
        for (int ks = 0; ks < 2; ks++) {
            uint32_t a[2][4];
#pragma unroll
            for (int mt = 0; mt < 2; mt++) {
                int rb = (wm * 32 + mt * 16 + gid) * TW + tg + ks * 8;
                a[mt][0] = A[rb];
                a[mt][1] = A[rb + 8 * TW];
                a[mt][2] = A[rb + 4];
                a[mt][3] = A[rb + 8 * TW + 4];
            }
#pragma unroll
            for (int nt = 0; nt < 4; nt++) {
                int bb = (wn * 32 + nt * 8 + gid) * TW + tg + ks * 8;
                uint32_t b0 = CV[bb], b1 = CV[bb + 4];
#pragma unroll
                for (int mt = 0; mt < 2; mt++) MMA_F16(acc[mt][nt], a[mt], b0, b1);
            }
        }
        __syncthreads();
    }

    // epilogue: atomic scaled scatter
#pragma unroll
    for (int mt = 0; mt < 2; mt++) {
#pragma unroll
        for (int half = 0; half < 2; half++) {
            int row = m0 + wm * 32 + mt * 16 + half * 8 + gid;
            if (row < cnt) {
                int slot = off + row;
                int tok = g_tok[slot];
                float coef = g_coef[slot];
                float* dst = out + (size_t)tok * H_DIM + n0 + wn * 32 + tg * 2;
#pragma unroll
                for (int nt = 0; nt < 4; nt++) {
                    atomicAdd(dst + nt * 8 + 0, acc[mt][nt][half * 2 + 0] * coef);
                    atomicAdd(dst + nt * 8 + 1, acc[mt][nt][half * 2 + 1] * coef);
                }
            }
        }
    }
}

// ================= launch =================
extern "C" void kernel_launch(void* const* d_in, const int* in_sizes, int n_in,
                              void* d_out, int out_size) {
    const float* x  = (const float*)d_in[0];
    const float* gw = (const float*)d_in[1];
    const float* w1 = (const float*)d_in[2];
    const float* w3 = (const float*)d_in[3];
    const float* w2 = (const float*)d_in[4];
    float* out = (float*)d_out;
    float* out_logits = out + (size_t)T_TOK * H_DIM;

    cudaFuncSetAttribute(gemm1_kernel, cudaFuncAttributeMaxDynamicSharedMemorySize, G1_SMEM);
    cudaFuncSetAttribute(gemm2_kernel, cudaFuncAttributeMaxDynamicSharedMemorySize, G2_SMEM);

    router_kernel<<<T_TOK / 8, 256>>>(x, gw, out, out_logits);
    route_scatter_kernel<<<1, 1024>>>();
    gemm1_kernel<<<dim3(F_DIM / 128, T_TOK / 128, E_NUM), 512, G1_SMEM>>>(w1, w3);
    gemm2_kernel<<<dim3(H_DIM / 128, T_TOK / 128, E_NUM * 4), 512, G2_SMEM>>>(w2, out);
}